// round 4
// baseline (speedup 1.0000x reference)
#include <cuda_runtime.h>
#include <math.h>

#define T_ 256
#define B_ 256
#define C_ 64
#define H_ 512
#define G_ 2048
#define K_ 640   // 512 (h) + 64 (c_c) + 64 (m)

// ---- static device scratch (no cudaMalloc allowed) ----
__device__ float g_v[T_*B_*C_];     // values time-major [t][b][c]
__device__ float g_m[T_*B_*C_];     // masks
__device__ float g_d[T_*B_*C_];     // deltas
__device__ float g_gh[T_*B_*H_];    // gamma_h precomputed (134MB)
__device__ float g_al[T_*B_*C_];    // alpha precomputed
__device__ float g_A[B_*K_];        // per-step GEMM A = [h_dec | c_c | m]
__device__ float g_h[B_*H_];        // hidden state
__device__ float g_c[B_*H_];        // cell state
__device__ float g_Wcat[G_*K_];     // permuted gate weights [u*4+gate][k]
__device__ float g_bias[G_];        // b_ih+b_hh permuted
__device__ float g_WhT[H_*C_];      // W_hist^T
__device__ float g_WfT[C_*C_];      // W_feat^T, zero diagonal
__device__ float g_WghT[C_*H_];     // W_gh^T
__device__ float g_WcT[2*C_*C_];    // W_comb^T
__device__ float g_diag[C_];        // diag(W_gx)

__global__ void k_pack_w(const float* __restrict__ Wih, const float* __restrict__ Whh) {
    for (int i = blockIdx.x*blockDim.x + threadIdx.x; i < G_*K_; i += gridDim.x*blockDim.x) {
        int gp = i / K_, k = i % K_;
        int u = gp >> 2, gate = gp & 3;
        int go = gate*H_ + u;   // PyTorch gate order i,f,g,o
        float w;
        if (k < H_)            w = Whh[go*H_ + k];
        else if (k < H_ + C_)  w = Wih[go*2*C_ + (k - H_)];
        else                   w = Wih[go*2*C_ + C_ + (k - H_ - C_)];
        g_Wcat[i] = w;
    }
}

__global__ void k_pack_misc(const float* __restrict__ Whist, const float* __restrict__ Wfeat,
                            const float* __restrict__ Wgh,   const float* __restrict__ Wcomb,
                            const float* __restrict__ bih,   const float* __restrict__ bhh,
                            const float* __restrict__ Wgx) {
    int tid = blockIdx.x*blockDim.x + threadIdx.x, n = gridDim.x*blockDim.x;
    for (int i = tid; i < H_*C_; i += n) { int u=i/C_, c=i%C_; g_WhT[i] = Whist[c*H_ + u]; }
    for (int i = tid; i < C_*C_; i += n) { int j=i/C_, c=i%C_; g_WfT[i] = (j==c)?0.f:Wfeat[c*C_ + j]; }
    for (int i = tid; i < C_*H_; i += n) { int c=i/H_, u=i%H_; g_WghT[i] = Wgh[u*C_ + c]; }
    for (int i = tid; i < 2*C_*C_; i += n) { int j=i/C_, c=i%C_; g_WcT[i] = Wcomb[c*2*C_ + j]; }
    for (int i = tid; i < C_; i += n) g_diag[i] = Wgx[i*C_ + i];
    for (int i = tid; i < G_; i += n) { int u=i>>2, g=i&3; int go=g*H_+u; g_bias[i] = bih[go] + bhh[go]; }
    for (int i = tid; i < B_*H_; i += n) { g_h[i] = 0.f; g_c[i] = 0.f; }
}

__global__ void k_prep(const float* __restrict__ data) {
    int id = blockIdx.x*blockDim.x + threadIdx.x;
    if (id >= B_*C_) return;
    int b = id / C_, c = id % C_;
    float dec = 1.f, m_prev = 1.f;
    for (int t = 0; t < T_; t++) {
        float x = data[(b*T_ + t)*C_ + c];
        float m = (x != x) ? 0.f : 1.f;
        float v = (x != x) ? 0.f : x;
        float del;
        if (t == 0) del = 0.f;
        else if (t == 1) del = 1.f;
        else { dec = (m_prev == 1.f) ? 1.f : dec + 1.f; del = dec; }
        int o = (t*B_ + b)*C_ + c;
        g_v[o] = v; g_m[o] = m; g_d[o] = del;
        m_prev = m;
    }
}

__global__ void k_gammaH(const float* __restrict__ bgh) {
    __shared__ float ds[C_];
    int row0 = blockIdx.x * 32;
    for (int r = 0; r < 32; r++) {
        int row = row0 + r;                  // row = t*B_ + b
        if (threadIdx.x < C_) ds[threadIdx.x] = g_d[row*C_ + threadIdx.x];
        __syncthreads();
        for (int u = threadIdx.x; u < H_; u += 256) {
            float acc = bgh[u];
            #pragma unroll 8
            for (int c = 0; c < C_; c++) acc += ds[c] * g_WghT[c*H_ + u];
            g_gh[row*H_ + u] = expf(-fmaxf(acc, 0.f));
        }
        __syncthreads();
    }
}

__global__ void k_alpha(const float* __restrict__ bgx, const float* __restrict__ bcomb) {
    __shared__ float gx[C_], ms[C_];
    int row0 = blockIdx.x * 8;
    int i = threadIdx.x;                     // 64 threads
    for (int r = 0; r < 8; r++) {
        int row = row0 + r;
        float d = g_d[row*C_ + i], m = g_m[row*C_ + i];
        gx[i] = expf(-fmaxf(d*g_diag[i] + bgx[i], 0.f));
        ms[i] = m;
        __syncthreads();
        float acc = bcomb[i];
        #pragma unroll 8
        for (int j = 0; j < C_; j++) acc += gx[j] * g_WcT[j*C_ + i];
        #pragma unroll 8
        for (int j = 0; j < C_; j++) acc += ms[j] * g_WcT[(C_ + j)*C_ + i];
        g_al[row*C_ + i] = acc;
        __syncthreads();
    }
}

// Phase A: per-row local work. 128 blocks x 2 rows, 256 threads.
__global__ void __launch_bounds__(256) k_phaseA(int t, const float* __restrict__ bhist,
                                                const float* __restrict__ bfeat,
                                                float* __restrict__ out) {
    __shared__ float hd[2*H_], xh[2*C_], xc[2*C_], ms[2*C_], vs[2*C_];
    int b0 = blockIdx.x * 2;
    int tid = threadIdx.x;
    if (tid < 128) {
        int r = tid >> 6, c = tid & 63;
        int o = (t*B_ + b0 + r)*C_ + c;
        ms[tid] = g_m[o]; vs[tid] = g_v[o];
    }
    #pragma unroll
    for (int e = 0; e < 4; e++) {
        int idx = e*256 + tid;               // 0..1023
        int r = idx >> 9, u = idx & 511;
        int b = b0 + r;
        float v = g_h[b*H_ + u] * g_gh[(t*B_ + b)*H_ + u];
        hd[idx] = v;
        g_A[b*K_ + u] = v;
    }
    __syncthreads();
    if (tid < 128) {
        int r = tid >> 6, c = tid & 63;
        float a0 = 0.f, a1 = 0.f, a2 = 0.f, a3 = 0.f;
        const float* hp = &hd[r*H_];
        #pragma unroll 4
        for (int u = 0; u < H_; u += 4) {
            a0 += hp[u+0] * g_WhT[(u+0)*C_ + c];
            a1 += hp[u+1] * g_WhT[(u+1)*C_ + c];
            a2 += hp[u+2] * g_WhT[(u+2)*C_ + c];
            a3 += hp[u+3] * g_WhT[(u+3)*C_ + c];
        }
        float x_h = a0 + a1 + a2 + a3 + bhist[c];
        xh[tid] = x_h;
        float m = ms[tid], v = vs[tid];
        xc[tid] = m*v + (1.f - m)*x_h;
    }
    __syncthreads();
    if (tid < 128) {
        int r = tid >> 6, i = tid & 63;
        int b = b0 + r;
        float z = bfeat[i];
        const float* xp = &xc[r*C_];
        #pragma unroll 8
        for (int j = 0; j < C_; j++) z += xp[j] * g_WfT[j*C_ + i];
        float al = g_al[(t*B_ + b)*C_ + i];
        float x_h = xh[tid];
        float ch = al*z + (1.f - al)*x_h;
        float m = ms[tid], v = vs[tid];
        float cc = m*v + (1.f - m)*ch;
        out[(b*T_ + t)*C_ + i] = cc;
        g_A[b*K_ + H_ + i] = cc;
        g_A[b*K_ + H_ + C_ + i] = m;
    }
}

// Phase B: gates GEMM [256x640]@[640x2048]^T + LSTM epilogue.
// 128 blocks: 4 M-tiles (64 rows) x 32 N-tiles (64 gate cols = 16 unit quadruples).
__global__ void __launch_bounds__(256) k_phaseB(int t) {
    __shared__ __align__(16) float As[32][68];
    __shared__ __align__(16) float Ws[32][68];
    int blk = blockIdx.x;
    int m0 = (blk & 3) * 64, n0 = (blk >> 2) * 64;
    int tid = threadIdx.x;
    int tx = tid & 15, ty = tid >> 4;
    float acc[4][4] = {};
    for (int kc = 0; kc < K_; kc += 32) {
        #pragma unroll
        for (int e = 0; e < 8; e++) {
            int idx = e*256 + tid;           // 0..2047
            int mm = idx >> 5, kk = idx & 31;
            As[kk][mm] = g_A[(m0 + mm)*K_ + kc + kk];
            Ws[kk][mm] = g_Wcat[(n0 + mm)*K_ + kc + kk];
        }
        __syncthreads();
        #pragma unroll
        for (int kk = 0; kk < 32; kk++) {
            float4 a = *(const float4*)&As[kk][tx*4];
            float4 w = *(const float4*)&Ws[kk][ty*4];
            acc[0][0] += a.x*w.x; acc[0][1] += a.x*w.y; acc[0][2] += a.x*w.z; acc[0][3] += a.x*w.w;
            acc[1][0] += a.y*w.x; acc[1][1] += a.y*w.y; acc[1][2] += a.y*w.z; acc[1][3] += a.y*w.w;
            acc[2][0] += a.z*w.x; acc[2][1] += a.z*w.y; acc[2][2] += a.z*w.z; acc[2][3] += a.z*w.w;
            acc[3][0] += a.w*w.x; acc[3][1] += a.w*w.y; acc[3][2] += a.w*w.z; acc[3][3] += a.w*w.w;
        }
        __syncthreads();
    }
    // epilogue: this thread's 4 N-cols = one unit's complete (i,f,g,o)
    int u  = (n0 + ty*4) >> 2;
    float bp0 = g_bias[n0 + ty*4 + 0];
    float bp1 = g_bias[n0 + ty*4 + 1];
    float bp2 = g_bias[n0 + ty*4 + 2];
    float bp3 = g_bias[n0 + ty*4 + 3];
    #pragma unroll
    for (int mi = 0; mi < 4; mi++) {
        int b = m0 + tx*4 + mi;
        float gi = acc[mi][0] + bp0;
        float gf = acc[mi][1] + bp1;
        float gg = acc[mi][2] + bp2;
        float go = acc[mi][3] + bp3;
        int idx = b*H_ + u;
        float co = g_c[idx];
        float si = 1.f/(1.f + expf(-gi));
        float sf = 1.f/(1.f + expf(-gf));
        float so = 1.f/(1.f + expf(-go));
        float cn = sf*co + si*tanhf(gg);
        g_c[idx] = cn;
        g_h[idx] = so*tanhf(cn);
    }
}

extern "C" void kernel_launch(void* const* d_in, const int* in_sizes, int n_in,
                              void* d_out, int out_size) {
    const float* data  = (const float*)d_in[0];
    const float* Wih   = (const float*)d_in[1];
    const float* Whh   = (const float*)d_in[2];
    const float* bih   = (const float*)d_in[3];
    const float* bhh   = (const float*)d_in[4];
    const float* Wgh   = (const float*)d_in[5];
    const float* bgh   = (const float*)d_in[6];
    const float* Wgx   = (const float*)d_in[7];
    const float* bgx   = (const float*)d_in[8];
    const float* Whist = (const float*)d_in[9];
    const float* bhist = (const float*)d_in[10];
    const float* Wfeat = (const float*)d_in[11];
    const float* bfeat = (const float*)d_in[12];
    const float* Wcomb = (const float*)d_in[13];
    const float* bcomb = (const float*)d_in[14];
    float* out = (float*)d_out;

    k_pack_w<<<2048, 256>>>(Wih, Whh);
    k_pack_misc<<<256, 256>>>(Whist, Wfeat, Wgh, Wcomb, bih, bhh, Wgx);
    k_prep<<<64, 256>>>(data);
    k_gammaH<<<2048, 256>>>(bgh);
    k_alpha<<<8192, 64>>>(bgx, bcomb);
    for (int t = 0; t < T_; t++) {
        k_phaseA<<<128, 256>>>(t, bhist, bfeat, out);
        k_phaseB<<<128, 256>>>(t);
    }
}

// round 6
// speedup vs baseline: 1.0914x; 1.0914x over previous
#include <cuda_runtime.h>
#include <math.h>

#define T_ 256
#define B_ 256
#define C_ 64
#define H_ 512
#define G_ 2048
#define K_ 640   // 512 (h) + 64 (c_c) + 64 (m)

// ---- static device scratch ----
__device__ float g_v[T_*B_*C_];
__device__ float g_m[T_*B_*C_];
__device__ float g_d[T_*B_*C_];
__device__ float g_gh[T_*B_*H_];    // gamma_h (134MB)
__device__ float g_al[T_*B_*C_];
__device__ float g_A[B_*K_];        // [h_dec | c_c | m]
__device__ float g_h[B_*H_];
__device__ float g_c[B_*H_];
__device__ float g_Wcat[G_*K_];     // [u*4+gate][k]
__device__ float g_bias[G_];
__device__ float g_WhT[H_*C_];
__device__ float g_WfT[C_*C_];
__device__ float g_WcT[2*C_*C_];
__device__ float g_diag[C_];

// ---- f32x2 packed FMA helpers ----
__device__ __forceinline__ unsigned long long dup2(float a) {
    unsigned long long r;
    asm("mov.b64 %0, {%1,%1};" : "=l"(r) : "f"(a));
    return r;
}
__device__ __forceinline__ void ffma2(unsigned long long& d, unsigned long long a,
                                      unsigned long long b) {
    asm("fma.rn.f32x2 %0, %1, %2, %0;" : "+l"(d) : "l"(a), "l"(b));
}
__device__ __forceinline__ float2 upk2(unsigned long long v) {
    float2 f;
    asm("mov.b64 {%0,%1}, %2;" : "=f"(f.x), "=f"(f.y) : "l"(v));
    return f;
}

__global__ void k_pack_w(const float* __restrict__ Wih, const float* __restrict__ Whh) {
    for (int i = blockIdx.x*blockDim.x + threadIdx.x; i < G_*K_; i += gridDim.x*blockDim.x) {
        int gp = i / K_, k = i % K_;
        int u = gp >> 2, gate = gp & 3;
        int go = gate*H_ + u;
        float w;
        if (k < H_)            w = Whh[go*H_ + k];
        else if (k < H_ + C_)  w = Wih[go*2*C_ + (k - H_)];
        else                   w = Wih[go*2*C_ + C_ + (k - H_ - C_)];
        g_Wcat[i] = w;
    }
}

__global__ void k_pack_misc(const float* __restrict__ Whist, const float* __restrict__ Wfeat,
                            const float* __restrict__ Wcomb, const float* __restrict__ bih,
                            const float* __restrict__ bhh,   const float* __restrict__ Wgx) {
    int tid = blockIdx.x*blockDim.x + threadIdx.x, n = gridDim.x*blockDim.x;
    for (int i = tid; i < H_*C_; i += n) { int u=i/C_, c=i%C_; g_WhT[i] = Whist[c*H_ + u]; }
    for (int i = tid; i < C_*C_; i += n) { int j=i/C_, c=i%C_; g_WfT[i] = (j==c)?0.f:Wfeat[c*C_ + j]; }
    for (int i = tid; i < 2*C_*C_; i += n) { int j=i/C_, c=i%C_; g_WcT[i] = Wcomb[c*2*C_ + j]; }
    for (int i = tid; i < C_; i += n) g_diag[i] = Wgx[i*C_ + i];
    for (int i = tid; i < G_; i += n) { int u=i>>2, g=i&3; int go=g*H_+u; g_bias[i] = bih[go] + bhh[go]; }
    for (int i = tid; i < B_*H_; i += n) { g_h[i] = 0.f; g_c[i] = 0.f; }
}

__global__ void k_prep(const float* __restrict__ data) {
    int id = blockIdx.x*blockDim.x + threadIdx.x;
    if (id >= B_*C_) return;
    int b = id / C_, c = id % C_;
    float dec = 1.f, m_prev = 1.f;
    for (int t = 0; t < T_; t++) {
        float x = data[(b*T_ + t)*C_ + c];
        float m = (x != x) ? 0.f : 1.f;
        float v = (x != x) ? 0.f : x;
        float del;
        if (t == 0) del = 0.f;
        else if (t == 1) del = 1.f;
        else { dec = (m_prev == 1.f) ? 1.f : dec + 1.f; del = dec; }
        int o = (t*B_ + b)*C_ + c;
        g_v[o] = v; g_m[o] = m; g_d[o] = del;
        m_prev = m;
    }
}

// gamma_h as a 64x64-tile GEMM: [65536 x 64] @ [64 x 512]^T (W_gh rows are K-contig)
__global__ void __launch_bounds__(256) k_gammaH(const float* __restrict__ Wgh,
                                                const float* __restrict__ bgh) {
    __shared__ __align__(16) float As[2][32][68];
    __shared__ __align__(16) float Ws[2][32][68];
    int m0 = (blockIdx.x >> 3) << 6;      // 1024 m-tiles (t*B+b rows)
    int n0 = (blockIdx.x & 7) << 6;       // 8 n-tiles (u)
    int tid = threadIdx.x, tx = tid & 15, ty = tid >> 4;
    int mm = tid >> 3, kk4 = (tid & 7) << 2;

    unsigned long long acc[4][2] = {};
    #define STAGE_G(buf, kc) { \
        float4 a0 = *(const float4*)&g_d[(m0+mm)*C_ + (kc) + kk4]; \
        float4 a1 = *(const float4*)&g_d[(m0+mm+32)*C_ + (kc) + kk4]; \
        float4 w0 = *(const float4*)&Wgh[(n0+mm)*C_ + (kc) + kk4]; \
        float4 w1 = *(const float4*)&Wgh[(n0+mm+32)*C_ + (kc) + kk4]; \
        As[buf][kk4+0][mm]=a0.x; As[buf][kk4+1][mm]=a0.y; As[buf][kk4+2][mm]=a0.z; As[buf][kk4+3][mm]=a0.w; \
        As[buf][kk4+0][mm+32]=a1.x; As[buf][kk4+1][mm+32]=a1.y; As[buf][kk4+2][mm+32]=a1.z; As[buf][kk4+3][mm+32]=a1.w; \
        Ws[buf][kk4+0][mm]=w0.x; Ws[buf][kk4+1][mm]=w0.y; Ws[buf][kk4+2][mm]=w0.z; Ws[buf][kk4+3][mm]=w0.w; \
        Ws[buf][kk4+0][mm+32]=w1.x; Ws[buf][kk4+1][mm+32]=w1.y; Ws[buf][kk4+2][mm+32]=w1.z; Ws[buf][kk4+3][mm+32]=w1.w; }

    STAGE_G(0, 0);
    __syncthreads();
    #pragma unroll
    for (int ch = 0; ch < 2; ch++) {
        int buf = ch & 1;
        if (ch < 1) STAGE_G(1, 32);
        #pragma unroll
        for (int kk = 0; kk < 32; kk++) {
            float4 a = *(const float4*)&As[buf][kk][tx*4];
            ulonglong2 w = *(const ulonglong2*)&Ws[buf][kk][ty*4];
            unsigned long long a0 = dup2(a.x), a1 = dup2(a.y), a2 = dup2(a.z), a3 = dup2(a.w);
            ffma2(acc[0][0], a0, w.x); ffma2(acc[0][1], a0, w.y);
            ffma2(acc[1][0], a1, w.x); ffma2(acc[1][1], a1, w.y);
            ffma2(acc[2][0], a2, w.x); ffma2(acc[2][1], a2, w.y);
            ffma2(acc[3][0], a3, w.x); ffma2(acc[3][1], a3, w.y);
        }
        __syncthreads();
    }
    int u0 = n0 + ty*4;
    float4 b4 = *(const float4*)&bgh[u0];
    #pragma unroll
    for (int mi = 0; mi < 4; mi++) {
        int row = m0 + tx*4 + mi;
        float2 p0 = upk2(acc[mi][0]), p1 = upk2(acc[mi][1]);
        float4 v;
        v.x = expf(-fmaxf(p0.x + b4.x, 0.f));
        v.y = expf(-fmaxf(p0.y + b4.y, 0.f));
        v.z = expf(-fmaxf(p1.x + b4.z, 0.f));
        v.w = expf(-fmaxf(p1.y + b4.w, 0.f));
        *(float4*)&g_gh[row*H_ + u0] = v;
    }
    #undef STAGE_G
}

__global__ void k_alpha(const float* __restrict__ bgx, const float* __restrict__ bcomb) {
    __shared__ float gx[4][C_], ms[4][C_];
    int row0 = blockIdx.x * 8;               // 8192 blocks x 8 rows = 65536 rows
    int r = threadIdx.x >> 6, i = threadIdx.x & 63;
    for (int p = 0; p < 2; p++) {
        int row = row0 + p*4 + r;
        float d = g_d[row*C_ + i], m = g_m[row*C_ + i];
        gx[r][i] = expf(-fmaxf(d*g_diag[i] + bgx[i], 0.f));
        ms[r][i] = m;
        __syncthreads();
        float acc = bcomb[i];
        #pragma unroll 8
        for (int j = 0; j < C_; j++) acc += gx[r][j] * g_WcT[j*C_ + i];
        #pragma unroll 8
        for (int j = 0; j < C_; j++) acc += ms[r][j] * g_WcT[(C_ + j)*C_ + i];
        g_al[row*C_ + i] = acc;
        __syncthreads();
    }
}

// Phase A: per-row local work. 128 blocks x 2 rows.
__global__ void __launch_bounds__(256) k_phaseA(int t, const float* __restrict__ bhist,
                                                const float* __restrict__ bfeat,
                                                float* __restrict__ out) {
    __shared__ float hd[2*H_], part[256], xh[2*C_], xc[2*C_], msh[2*C_], vsh[2*C_];
    int b0 = blockIdx.x * 2;
    int tid = threadIdx.x;
    if (tid < 128) {
        int r = tid >> 6, c = tid & 63;
        int o = (t*B_ + b0 + r)*C_ + c;
        msh[tid] = g_m[o]; vsh[tid] = g_v[o];
    }
    {
        int r = tid >> 7, u0 = (tid & 127) * 4;
        int b = b0 + r;
        float4 h4 = *(const float4*)&g_h[b*H_ + u0];
        float4 gh4 = *(const float4*)&g_gh[(t*B_ + b)*H_ + u0];
        float4 v = make_float4(h4.x*gh4.x, h4.y*gh4.y, h4.z*gh4.z, h4.w*gh4.w);
        *(float4*)&hd[r*H_ + u0] = v;
        *(float4*)&g_A[b*K_ + u0] = v;
    }
    __syncthreads();
    {   // x_h GEMV: 256 threads = 2 rows x 2 u-halves x 64 c
        int r = tid >> 7, half = (tid >> 6) & 1, c = tid & 63;
        const float* hp = &hd[r*H_ + half*256];
        const float* wp = &g_WhT[(half*256)*C_ + c];
        float a0 = 0.f, a1 = 0.f, a2 = 0.f, a3 = 0.f;
        #pragma unroll 8
        for (int u = 0; u < 256; u += 4) {
            a0 += hp[u+0] * wp[(u+0)*C_];
            a1 += hp[u+1] * wp[(u+1)*C_];
            a2 += hp[u+2] * wp[(u+2)*C_];
            a3 += hp[u+3] * wp[(u+3)*C_];
        }
        part[tid] = (a0 + a1) + (a2 + a3);
    }
    __syncthreads();
    if (tid < 128) {
        int r = tid >> 6, c = tid & 63;
        float x_h = part[r*128 + c] + part[r*128 + 64 + c] + bhist[c];
        xh[tid] = x_h;
        float m = msh[tid], v = vsh[tid];
        xc[tid] = m*v + (1.f - m)*x_h;
    }
    __syncthreads();
    if (tid < 128) {
        int r = tid >> 6, i = tid & 63;
        int b = b0 + r;
        float z = bfeat[i];
        const float* xp = &xc[r*C_];
        #pragma unroll 8
        for (int j = 0; j < C_; j++) z += xp[j] * g_WfT[j*C_ + i];
        float al = g_al[(t*B_ + b)*C_ + i];
        float x_h = xh[tid];
        float ch = al*z + (1.f - al)*x_h;
        float m = msh[tid], v = vsh[tid];
        float cc = m*v + (1.f - m)*ch;
        out[(b*T_ + t)*C_ + i] = cc;
        g_A[b*K_ + H_ + i] = cc;
        g_A[b*K_ + H_ + C_ + i] = m;
    }
}

// Phase B: [256x640]@[640x2048]^T + LSTM epilogue. f32x2, double-buffered.
__global__ void __launch_bounds__(256) k_phaseB(int t) {
    __shared__ __align__(16) float As[2][32][68];
    __shared__ __align__(16) float Ws[2][32][68];
    int m0 = (blockIdx.x & 3) << 6, n0 = (blockIdx.x >> 2) << 6;
    int tid = threadIdx.x, tx = tid & 15, ty = tid >> 4;
    int mm = tid >> 3, kk4 = (tid & 7) << 2;

    unsigned long long acc[4][2] = {};
    #define STAGE_B(buf, kc) { \
        float4 a0 = *(const float4*)&g_A[(m0+mm)*K_ + (kc) + kk4]; \
        float4 a1 = *(const float4*)&g_A[(m0+mm+32)*K_ + (kc) + kk4]; \
        float4 w0 = *(const float4*)&g_Wcat[(n0+mm)*K_ + (kc) + kk4]; \
        float4 w1 = *(const float4*)&g_Wcat[(n0+mm+32)*K_ + (kc) + kk4]; \
        As[buf][kk4+0][mm]=a0.x; As[buf][kk4+1][mm]=a0.y; As[buf][kk4+2][mm]=a0.z; As[buf][kk4+3][mm]=a0.w; \
        As[buf][kk4+0][mm+32]=a1.x; As[buf][kk4+1][mm+32]=a1.y; As[buf][kk4+2][mm+32]=a1.z; As[buf][kk4+3][mm+32]=a1.w; \
        Ws[buf][kk4+0][mm]=w0.x; Ws[buf][kk4+1][mm]=w0.y; Ws[buf][kk4+2][mm]=w0.z; Ws[buf][kk4+3][mm]=w0.w; \
        Ws[buf][kk4+0][mm+32]=w1.x; Ws[buf][kk4+1][mm+32]=w1.y; Ws[buf][kk4+2][mm+32]=w1.z; Ws[buf][kk4+3][mm+32]=w1.w; }

    STAGE_B(0, 0);
    __syncthreads();
    for (int ch = 0; ch < 20; ch++) {
        int buf = ch & 1;
        if (ch < 19) STAGE_B(buf ^ 1, (ch + 1) * 32);
        #pragma unroll
        for (int kk = 0; kk < 32; kk++) {
            float4 a = *(const float4*)&As[buf][kk][tx*4];
            ulonglong2 w = *(const ulonglong2*)&Ws[buf][kk][ty*4];
            unsigned long long a0 = dup2(a.x), a1 = dup2(a.y), a2 = dup2(a.z), a3 = dup2(a.w);
            ffma2(acc[0][0], a0, w.x); ffma2(acc[0][1], a0, w.y);
            ffma2(acc[1][0], a1, w.x); ffma2(acc[1][1], a1, w.y);
            ffma2(acc[2][0], a2, w.x); ffma2(acc[2][1], a2, w.y);
            ffma2(acc[3][0], a3, w.x); ffma2(acc[3][1], a3, w.y);
        }
        __syncthreads();
    }
    #undef STAGE_B
    // epilogue: this thread's 4 N-cols = one unit's (i,f,g,o)
    int u = (n0 + ty*4) >> 2;
    float4 bq = *(const float4*)&g_bias[n0 + ty*4];
    #pragma unroll
    for (int mi = 0; mi < 4; mi++) {
        int b = m0 + tx*4 + mi;
        float2 p0 = upk2(acc[mi][0]), p1 = upk2(acc[mi][1]);
        float gi = p0.x + bq.x;
        float gf = p0.y + bq.y;
        float gg = p1.x + bq.z;
        float go = p1.y + bq.w;
        int idx = b*H_ + u;
        float co = g_c[idx];
        float si = 1.f/(1.f + expf(-gi));
        float sf = 1.f/(1.f + expf(-gf));
        float so = 1.f/(1.f + expf(-go));
        float cn = sf*co + si*tanhf(gg);
        g_c[idx] = cn;
        g_h[idx] = so*tanhf(cn);
    }
}

extern "C" void kernel_launch(void* const* d_in, const int* in_sizes, int n_in,
                              void* d_out, int out_size) {
    const float* data  = (const float*)d_in[0];
    const float* Wih   = (const float*)d_in[1];
    const float* Whh   = (const float*)d_in[2];
    const float* bih   = (const float*)d_in[3];
    const float* bhh   = (const float*)d_in[4];
    const float* Wgh   = (const float*)d_in[5];
    const float* bgh   = (const float*)d_in[6];
    const float* Wgx   = (const float*)d_in[7];
    const float* bgx   = (const float*)d_in[8];
    const float* Whist = (const float*)d_in[9];
    const float* bhist = (const float*)d_in[10];
    const float* Wfeat = (const float*)d_in[11];
    const float* bfeat = (const float*)d_in[12];
    const float* Wcomb = (const float*)d_in[13];
    const float* bcomb = (const float*)d_in[14];
    float* out = (float*)d_out;

    k_pack_w<<<2048, 256>>>(Wih, Whh);
    k_pack_misc<<<256, 256>>>(Whist, Wfeat, Wcomb, bih, bhh, Wgx);
    k_prep<<<64, 256>>>(data);
    k_gammaH<<<8192, 256>>>(Wgh, bgh);
    k_alpha<<<8192, 256>>>(bgx, bcomb);   // FIX: full 65536-row coverage
    for (int t = 0; t < T_; t++) {
        k_phaseA<<<128, 256>>>(t, bhist, bfeat, out);
        k_phaseB<<<128, 256>>>(t);
    }
}

// round 7
// speedup vs baseline: 1.3499x; 1.2368x over previous
#include <cuda_runtime.h>
#include <math.h>

#define T_ 256
#define B_ 256
#define C_ 64
#define H_ 512
#define G_ 2048
#define K_ 640   // 512 (h) + 64 (c_c) + 64 (m)
#define NBLK 128

// ---- static device scratch ----
__device__ float g_v[T_*B_*C_];
__device__ float g_m[T_*B_*C_];
__device__ float g_d[T_*B_*C_];
__device__ float g_gh[T_*B_*H_];    // gamma_h (134MB)
__device__ float g_al[T_*B_*C_];
__device__ float g_A[B_*K_];        // [h_dec | c_c | m]
__device__ float g_h[B_*H_];
__device__ float g_Wcat[G_*K_];     // [u*4+gate][k]
__device__ float g_bias[G_];
__device__ float g_WhT[H_*C_];
__device__ float g_WfT[C_*C_];
__device__ float g_WcT[2*C_*C_];
__device__ float g_diag[C_];
__device__ unsigned g_arrive;
__device__ unsigned g_gen;

// ---- f32x2 packed FMA helpers ----
__device__ __forceinline__ unsigned long long dup2(float a) {
    unsigned long long r;
    asm("mov.b64 %0, {%1,%1};" : "=l"(r) : "f"(a));
    return r;
}
__device__ __forceinline__ void ffma2(unsigned long long& d, unsigned long long a,
                                      unsigned long long b) {
    asm("fma.rn.f32x2 %0, %1, %2, %0;" : "+l"(d) : "l"(a), "l"(b));
}
__device__ __forceinline__ float2 upk2(unsigned long long v) {
    float2 f;
    asm("mov.b64 {%0,%1}, %2;" : "=f"(f.x), "=f"(f.y) : "l"(v));
    return f;
}

// ---- grid barrier (sense via generation counter; leaves arrive==0 at exit) ----
__device__ __forceinline__ void gbar() {
    __threadfence();          // publish stores + invalidate this SM's L1
    __syncthreads();
    if (threadIdx.x == 0) {
        unsigned gen = atomicAdd(&g_gen, 0u);
        unsigned a = atomicAdd(&g_arrive, 1u);
        if (a == NBLK - 1) {
            atomicExch(&g_arrive, 0u);
            __threadfence();
            atomicAdd(&g_gen, 1u);
        } else {
            while (atomicAdd(&g_gen, 0u) == gen) __nanosleep(64);
        }
    }
    __syncthreads();
}

// ======================= preamble kernels (unchanged from R6) =======================

__global__ void k_pack_w(const float* __restrict__ Wih, const float* __restrict__ Whh) {
    for (int i = blockIdx.x*blockDim.x + threadIdx.x; i < G_*K_; i += gridDim.x*blockDim.x) {
        int gp = i / K_, k = i % K_;
        int u = gp >> 2, gate = gp & 3;
        int go = gate*H_ + u;
        float w;
        if (k < H_)            w = Whh[go*H_ + k];
        else if (k < H_ + C_)  w = Wih[go*2*C_ + (k - H_)];
        else                   w = Wih[go*2*C_ + C_ + (k - H_ - C_)];
        g_Wcat[i] = w;
    }
}

__global__ void k_pack_misc(const float* __restrict__ Whist, const float* __restrict__ Wfeat,
                            const float* __restrict__ Wcomb, const float* __restrict__ bih,
                            const float* __restrict__ bhh,   const float* __restrict__ Wgx) {
    int tid = blockIdx.x*blockDim.x + threadIdx.x, n = gridDim.x*blockDim.x;
    for (int i = tid; i < H_*C_; i += n) { int u=i/C_, c=i%C_; g_WhT[i] = Whist[c*H_ + u]; }
    for (int i = tid; i < C_*C_; i += n) { int j=i/C_, c=i%C_; g_WfT[i] = (j==c)?0.f:Wfeat[c*C_ + j]; }
    for (int i = tid; i < 2*C_*C_; i += n) { int j=i/C_, c=i%C_; g_WcT[i] = Wcomb[c*2*C_ + j]; }
    for (int i = tid; i < C_; i += n) g_diag[i] = Wgx[i*C_ + i];
    for (int i = tid; i < G_; i += n) { int u=i>>2, g=i&3; int go=g*H_+u; g_bias[i] = bih[go] + bhh[go]; }
    for (int i = tid; i < B_*H_; i += n) g_h[i] = 0.f;
}

__global__ void k_prep(const float* __restrict__ data) {
    int id = blockIdx.x*blockDim.x + threadIdx.x;
    if (id >= B_*C_) return;
    int b = id / C_, c = id % C_;
    float dec = 1.f, m_prev = 1.f;
    for (int t = 0; t < T_; t++) {
        float x = data[(b*T_ + t)*C_ + c];
        float m = (x != x) ? 0.f : 1.f;
        float v = (x != x) ? 0.f : x;
        float del;
        if (t == 0) del = 0.f;
        else if (t == 1) del = 1.f;
        else { dec = (m_prev == 1.f) ? 1.f : dec + 1.f; del = dec; }
        int o = (t*B_ + b)*C_ + c;
        g_v[o] = v; g_m[o] = m; g_d[o] = del;
        m_prev = m;
    }
}

__global__ void __launch_bounds__(256) k_gammaH(const float* __restrict__ Wgh,
                                                const float* __restrict__ bgh) {
    __shared__ __align__(16) float As[2][32][68];
    __shared__ __align__(16) float Ws[2][32][68];
    int m0 = (blockIdx.x >> 3) << 6;
    int n0 = (blockIdx.x & 7) << 6;
    int tid = threadIdx.x, tx = tid & 15, ty = tid >> 4;
    int mm = tid >> 3, kk4 = (tid & 7) << 2;

    unsigned long long acc[4][2] = {};
    #define STAGE_G(buf, kc) { \
        float4 a0 = *(const float4*)&g_d[(m0+mm)*C_ + (kc) + kk4]; \
        float4 a1 = *(const float4*)&g_d[(m0+mm+32)*C_ + (kc) + kk4]; \
        float4 w0 = *(const float4*)&Wgh[(n0+mm)*C_ + (kc) + kk4]; \
        float4 w1 = *(const float4*)&Wgh[(n0+mm+32)*C_ + (kc) + kk4]; \
        As[buf][kk4+0][mm]=a0.x; As[buf][kk4+1][mm]=a0.y; As[buf][kk4+2][mm]=a0.z; As[buf][kk4+3][mm]=a0.w; \
        As[buf][kk4+0][mm+32]=a1.x; As[buf][kk4+1][mm+32]=a1.y; As[buf][kk4+2][mm+32]=a1.z; As[buf][kk4+3][mm+32]=a1.w; \
        Ws[buf][kk4+0][mm]=w0.x; Ws[buf][kk4+1][mm]=w0.y; Ws[buf][kk4+2][mm]=w0.z; Ws[buf][kk4+3][mm]=w0.w; \
        Ws[buf][kk4+0][mm+32]=w1.x; Ws[buf][kk4+1][mm+32]=w1.y; Ws[buf][kk4+2][mm+32]=w1.z; Ws[buf][kk4+3][mm+32]=w1.w; }

    STAGE_G(0, 0);
    __syncthreads();
    #pragma unroll
    for (int ch = 0; ch < 2; ch++) {
        int buf = ch & 1;
        if (ch < 1) STAGE_G(1, 32);
        #pragma unroll
        for (int kk = 0; kk < 32; kk++) {
            float4 a = *(const float4*)&As[buf][kk][tx*4];
            ulonglong2 w = *(const ulonglong2*)&Ws[buf][kk][ty*4];
            unsigned long long a0 = dup2(a.x), a1 = dup2(a.y), a2 = dup2(a.z), a3 = dup2(a.w);
            ffma2(acc[0][0], a0, w.x); ffma2(acc[0][1], a0, w.y);
            ffma2(acc[1][0], a1, w.x); ffma2(acc[1][1], a1, w.y);
            ffma2(acc[2][0], a2, w.x); ffma2(acc[2][1], a2, w.y);
            ffma2(acc[3][0], a3, w.x); ffma2(acc[3][1], a3, w.y);
        }
        __syncthreads();
    }
    int u0 = n0 + ty*4;
    float4 b4 = *(const float4*)&bgh[u0];
    #pragma unroll
    for (int mi = 0; mi < 4; mi++) {
        int row = m0 + tx*4 + mi;
        float2 p0 = upk2(acc[mi][0]), p1 = upk2(acc[mi][1]);
        float4 v;
        v.x = expf(-fmaxf(p0.x + b4.x, 0.f));
        v.y = expf(-fmaxf(p0.y + b4.y, 0.f));
        v.z = expf(-fmaxf(p1.x + b4.z, 0.f));
        v.w = expf(-fmaxf(p1.y + b4.w, 0.f));
        *(float4*)&g_gh[row*H_ + u0] = v;
    }
    #undef STAGE_G
}

__global__ void k_alpha(const float* __restrict__ bgx, const float* __restrict__ bcomb) {
    __shared__ float gx[4][C_], ms[4][C_];
    int row0 = blockIdx.x * 8;
    int r = threadIdx.x >> 6, i = threadIdx.x & 63;
    for (int p = 0; p < 2; p++) {
        int row = row0 + p*4 + r;
        float d = g_d[row*C_ + i], m = g_m[row*C_ + i];
        gx[r][i] = expf(-fmaxf(d*g_diag[i] + bgx[i], 0.f));
        ms[r][i] = m;
        __syncthreads();
        float acc = bcomb[i];
        #pragma unroll 8
        for (int j = 0; j < C_; j++) acc += gx[r][j] * g_WcT[j*C_ + i];
        #pragma unroll 8
        for (int j = 0; j < C_; j++) acc += ms[r][j] * g_WcT[(C_ + j)*C_ + i];
        g_al[row*C_ + i] = acc;
        __syncthreads();
    }
}

// ======================= persistent sequential kernel =======================
// dynamic smem layout (floats):
#define SW_OFF   0                       // W slice [640][68-pitch], 64 cols used
#define SW_SZ    (K_*68)                 // 43520
#define AS_OFF   (SW_OFF + SW_SZ)        // A staging, double buffered
#define AS_SZ    (2*32*68)               // 4352
#define HD_OFF   (AS_OFF + AS_SZ)        // 2*512
#define PART_OFF (HD_OFF + 2*H_)         // 256
#define XH_OFF   (PART_OFF + 256)
#define XC_OFF   (XH_OFF + 2*C_)
#define MS_OFF   (XC_OFF + 2*C_)
#define VS_OFF   (MS_OFF + 2*C_)
#define SMEM_FLOATS (VS_OFF + 2*C_)      // 49664 floats = 198656 B

__global__ void __launch_bounds__(256, 1) k_seq(const float* __restrict__ bhist,
                                                const float* __restrict__ bfeat,
                                                float* __restrict__ out) {
    extern __shared__ __align__(16) float sm[];
    float* Wsm  = sm + SW_OFF;
    float* As   = sm + AS_OFF;
    float* hd   = sm + HD_OFF;
    float* part = sm + PART_OFF;
    float* xh   = sm + XH_OFF;
    float* xc   = sm + XC_OFF;
    float* msh  = sm + MS_OFF;
    float* vsh  = sm + VS_OFF;

    int tid = threadIdx.x, blk = blockIdx.x;
    int m0 = (blk & 3) << 6, n0 = (blk >> 2) << 6;   // phase-B tile
    int tx = tid & 15, ty = tid >> 4;
    int mm = tid >> 3, kk4 = (tid & 7) << 2;
    int b0 = blk * 2;                                 // phase-A rows

    // prologue: load this block's W slice into smem (once), bias into regs
    for (int i = tid; i < 64*K_; i += 256) {
        int nl = i / K_, k = i - nl*K_;
        Wsm[k*68 + nl] = g_Wcat[(n0 + nl)*K_ + k];
    }
    float4 bq = *(const float4*)&g_bias[n0 + ty*4];
    int u_ep = (n0 + ty*4) >> 2;                     // this thread's LSTM unit
    float cst[4] = {0.f, 0.f, 0.f, 0.f};             // cell state in registers
    __syncthreads();

    for (int t = 0; t < T_; t++) {
        // ---------------- phase A: rows b0, b0+1 ----------------
        if (tid < 128) {
            int r = tid >> 6, c = tid & 63;
            int o = (t*B_ + b0 + r)*C_ + c;
            msh[tid] = g_m[o]; vsh[tid] = g_v[o];
        }
        {
            int r = tid >> 7, u0 = (tid & 127) * 4;
            int b = b0 + r;
            float4 h4 = *(const float4*)&g_h[b*H_ + u0];
            float4 gh4 = *(const float4*)&g_gh[(t*B_ + b)*H_ + u0];
            float4 v = make_float4(h4.x*gh4.x, h4.y*gh4.y, h4.z*gh4.z, h4.w*gh4.w);
            *(float4*)&hd[r*H_ + u0] = v;
            *(float4*)&g_A[b*K_ + u0] = v;
        }
        __syncthreads();
        {   // x_h GEMV: 2 rows x 2 u-halves x 64 c
            int r = tid >> 7, half = (tid >> 6) & 1, c = tid & 63;
            const float* hp = &hd[r*H_ + half*256];
            const float* wp = &g_WhT[(half*256)*C_ + c];
            float a0 = 0.f, a1 = 0.f, a2 = 0.f, a3 = 0.f;
            #pragma unroll 8
            for (int u = 0; u < 256; u += 4) {
                a0 += hp[u+0] * wp[(u+0)*C_];
                a1 += hp[u+1] * wp[(u+1)*C_];
                a2 += hp[u+2] * wp[(u+2)*C_];
                a3 += hp[u+3] * wp[(u+3)*C_];
            }
            part[tid] = (a0 + a1) + (a2 + a3);
        }
        __syncthreads();
        if (tid < 128) {
            int r = tid >> 6, c = tid & 63;
            float x_h = part[r*128 + c] + part[r*128 + 64 + c] + bhist[c];
            xh[tid] = x_h;
            float m = msh[tid], v = vsh[tid];
            xc[tid] = m*v + (1.f - m)*x_h;
        }
        __syncthreads();
        if (tid < 128) {
            int r = tid >> 6, i = tid & 63;
            int b = b0 + r;
            float z = bfeat[i];
            const float* xp = &xc[r*C_];
            #pragma unroll 8
            for (int j = 0; j < C_; j++) z += xp[j] * g_WfT[j*C_ + i];
            float al = g_al[(t*B_ + b)*C_ + i];
            float x_h = xh[tid];
            float ch = al*z + (1.f - al)*x_h;
            float m = msh[tid], v = vsh[tid];
            float cc = m*v + (1.f - m)*ch;
            out[(b*T_ + t)*C_ + i] = cc;
            g_A[b*K_ + H_ + i] = cc;
            g_A[b*K_ + H_ + C_ + i] = m;
        }
        gbar();   // g_A complete chip-wide

        // ---------------- phase B: 64x64 tile of [256x640]@[640x2048]^T ----------------
        unsigned long long acc[4][2] = {};
        #define STAGE_A(buf, kc) { \
            float4 a0 = *(const float4*)&g_A[(m0+mm)*K_ + (kc) + kk4]; \
            float4 a1 = *(const float4*)&g_A[(m0+mm+32)*K_ + (kc) + kk4]; \
            float* Ab = As + (buf)*(32*68); \
            Ab[(kk4+0)*68+mm]=a0.x; Ab[(kk4+1)*68+mm]=a0.y; Ab[(kk4+2)*68+mm]=a0.z; Ab[(kk4+3)*68+mm]=a0.w; \
            Ab[(kk4+0)*68+mm+32]=a1.x; Ab[(kk4+1)*68+mm+32]=a1.y; Ab[(kk4+2)*68+mm+32]=a1.z; Ab[(kk4+3)*68+mm+32]=a1.w; }

        STAGE_A(0, 0);
        __syncthreads();
        for (int ch = 0; ch < 20; ch++) {
            int buf = ch & 1;
            if (ch < 19) STAGE_A(buf ^ 1, (ch + 1) * 32);
            const float* Ab = As + buf*(32*68);
            const float* Wb = Wsm + (ch*32)*68;
            #pragma unroll
            for (int kk = 0; kk < 32; kk++) {
                float4 a = *(const float4*)&Ab[kk*68 + tx*4];
                ulonglong2 w = *(const ulonglong2*)&Wb[kk*68 + ty*4];
                unsigned long long a0 = dup2(a.x), a1 = dup2(a.y), a2 = dup2(a.z), a3 = dup2(a.w);
                ffma2(acc[0][0], a0, w.x); ffma2(acc[0][1], a0, w.y);
                ffma2(acc[1][0], a1, w.x); ffma2(acc[1][1], a1, w.y);
                ffma2(acc[2][0], a2, w.x); ffma2(acc[2][1], a2, w.y);
                ffma2(acc[3][0], a3, w.x); ffma2(acc[3][1], a3, w.y);
            }
            __syncthreads();
        }
        #undef STAGE_A

        // LSTM epilogue: each thread owns unit u_ep for 4 batch rows
        #pragma unroll
        for (int mi = 0; mi < 4; mi++) {
            int b = m0 + tx*4 + mi;
            float2 p0 = upk2(acc[mi][0]), p1 = upk2(acc[mi][1]);
            float gi = p0.x + bq.x;
            float gf = p0.y + bq.y;
            float gg = p1.x + bq.z;
            float go = p1.y + bq.w;
            float co = cst[mi];
            float si = 1.f/(1.f + expf(-gi));
            float sf = 1.f/(1.f + expf(-gf));
            float so = 1.f/(1.f + expf(-go));
            float cn = sf*co + si*tanhf(gg);
            cst[mi] = cn;
            g_h[b*H_ + u_ep] = so*tanhf(cn);
        }
        gbar();   // g_h complete chip-wide
    }
}

extern "C" void kernel_launch(void* const* d_in, const int* in_sizes, int n_in,
                              void* d_out, int out_size) {
    const float* data  = (const float*)d_in[0];
    const float* Wih   = (const float*)d_in[1];
    const float* Whh   = (const float*)d_in[2];
    const float* bih   = (const float*)d_in[3];
    const float* bhh   = (const float*)d_in[4];
    const float* Wgh   = (const float*)d_in[5];
    const float* bgh   = (const float*)d_in[6];
    const float* Wgx   = (const float*)d_in[7];
    const float* bgx   = (const float*)d_in[8];
    const float* Whist = (const float*)d_in[9];
    const float* bhist = (const float*)d_in[10];
    const float* Wfeat = (const float*)d_in[11];
    const float* bfeat = (const float*)d_in[12];
    const float* Wcomb = (const float*)d_in[13];
    const float* bcomb = (const float*)d_in[14];
    float* out = (float*)d_out;

    static int smem_set = 0;
    if (!smem_set) {
        cudaFuncSetAttribute(k_seq, cudaFuncAttributeMaxDynamicSharedMemorySize,
                             SMEM_FLOATS * sizeof(float));
        smem_set = 1;
    }

    k_pack_w<<<2048, 256>>>(Wih, Whh);
    k_pack_misc<<<256, 256>>>(Whist, Wfeat, Wcomb, bih, bhh, Wgx);
    k_prep<<<64, 256>>>(data);
    k_gammaH<<<8192, 256>>>(Wgh, bgh);
    k_alpha<<<8192, 256>>>(bgx, bcomb);
    k_seq<<<NBLK, 256, SMEM_FLOATS * sizeof(float)>>>(bhist, bfeat, out);
}